// round 13
// baseline (speedup 1.0000x reference)
#include <cuda_runtime.h>

// Problem constants (fixed by setup_inputs: img [1,1,544,960], T=8, R=4)
#define H  544
#define W  960
#define T  8
#define R  4
#define HB (H/T)                  // 68
#define WB (W/T)                  // 120
#define NB (HB*WB)                // 8160
#define NC ((2*R+1)*(2*R+1))      // 81

// ---------------- scratch (device globals) ----------------------------------
__device__ float         g_cur_blur[H*W];
__device__ unsigned char g_cur_q[H*W];
__device__ unsigned char g_prev_q[H*W];

// spiral rank LUT (row-major over (dy+R, dx+R)), precomputed for R=4
__constant__ unsigned char c_spiral[NC] = {
    74, 73, 72, 71, 70, 69, 68, 67, 66,
    75, 44, 43, 42, 41, 40, 39, 38, 65,
    76, 45, 22, 21, 20, 19, 18, 37, 64,
    77, 46, 23,  8,  7,  6, 17, 36, 63,
    78, 47, 24,  9,  1,  5, 16, 35, 62,
    79, 48, 25,  2,  3,  4, 15, 34, 61,
    80, 49, 10, 11, 12, 13, 14, 33, 60,
    81, 26, 27, 28, 29, 30, 31, 32, 59,
    50, 51, 52, 53, 54, 55, 56, 57, 58
};

__device__ __forceinline__ unsigned char quant8(float v) {
    return (unsigned char)fminf(fmaxf(rintf(v * 255.0f), 0.0f), 255.0f);
}
__device__ __forceinline__ int clampi(int v, int lo, int hi) {
    return min(max(v, lo), hi);
}

// ================= kernel 1: binomial blur + quantize (R9, proven) ===========
__global__ void __launch_bounds__(256) blur_kernel(const float* __restrict__ cur,
                                                   const float* __restrict__ prev) {
    const int lane = threadIdx.x;
    const int x2   = (blockIdx.x * 32 + lane) * 2;            // W = 15*64
    const int y    = blockIdx.y * 8 + threadIdx.y;            // H = 68*8
    const int yu = max(y - 1, 0) * W;
    const int ym = y * W;
    const int yd = min(y + 1, H - 1) * W;
    const bool eL = (lane == 0), eR = (lane == 31);
    const int xe = eL ? max(x2 - 1, 0) : min(x2 + 2, W - 1);

    float2 u0 = *(const float2*)&cur [yu + x2];
    float2 m0 = *(const float2*)&cur [ym + x2];
    float2 d0 = *(const float2*)&cur [yd + x2];
    float2 u1 = *(const float2*)&prev[yu + x2];
    float2 m1 = *(const float2*)&prev[ym + x2];
    float2 d1 = *(const float2*)&prev[yd + x2];
    float eu0 = 0.f, em0 = 0.f, ed0 = 0.f, eu1 = 0.f, em1 = 0.f, ed1 = 0.f;
    if (eL || eR) {
        eu0 = cur [yu + xe]; em0 = cur [ym + xe]; ed0 = cur [yd + xe];
        eu1 = prev[yu + xe]; em1 = prev[ym + xe]; ed1 = prev[yd + xe];
    }
    {
        float v0 = (u0.x + 2.0f * m0.x + d0.x) * 0.25f;
        float v1 = (u0.y + 2.0f * m0.y + d0.y) * 0.25f;
        float ve = (eu0 + 2.0f * em0 + ed0) * 0.25f;
        float vL = __shfl_up_sync(0xffffffffu, v1, 1);
        float vR = __shfl_down_sync(0xffffffffu, v0, 1);
        if (eL) vL = ve;
        if (eR) vR = ve;
        float o0 = (vL + 2.0f * v0 + v1) * 0.25f;
        float o1 = (v0 + 2.0f * v1 + vR) * 0.25f;
        *(float2*)&g_cur_blur[ym + x2] = make_float2(o0, o1);
        *(uchar2*)&g_cur_q[ym + x2]    = make_uchar2(quant8(o0), quant8(o1));
    }
    {
        float v0 = (u1.x + 2.0f * m1.x + d1.x) * 0.25f;
        float v1 = (u1.y + 2.0f * m1.y + d1.y) * 0.25f;
        float ve = (eu1 + 2.0f * em1 + ed1) * 0.25f;
        float vL = __shfl_up_sync(0xffffffffu, v1, 1);
        float vR = __shfl_down_sync(0xffffffffu, v0, 1);
        if (eL) vL = ve;
        if (eR) vR = ve;
        float o0 = (vL + 2.0f * v0 + v1) * 0.25f;
        float o1 = (v0 + 2.0f * v1 + vR) * 0.25f;
        *(uchar2*)&g_prev_q[ym + x2]   = make_uchar2(quant8(o0), quant8(o1));
    }
    cudaTriggerProgrammaticLaunchCompletion();
}

// ---------------- packed byte-SIMD median of 9 (Paeth network) --------------
#define SWU(a,b) { unsigned _t = __vminu4(a,b); b = __vmaxu4(a,b); a = _t; }
__device__ __forceinline__ unsigned med9u(unsigned v0, unsigned v1, unsigned v2,
                                          unsigned v3, unsigned v4, unsigned v5,
                                          unsigned v6, unsigned v7, unsigned v8) {
    SWU(v1,v2) SWU(v4,v5) SWU(v7,v8)
    SWU(v0,v1) SWU(v3,v4) SWU(v6,v7)
    SWU(v1,v2) SWU(v4,v5) SWU(v7,v8)
    SWU(v0,v3) SWU(v5,v8) SWU(v4,v7)
    SWU(v3,v6) SWU(v1,v4) SWU(v2,v5)
    SWU(v4,v7) SWU(v4,v2) SWU(v6,v4)
    SWU(v4,v2)
    return v4;
}

// ===== kernel 2: redundant match (4x10 block nbhd) + median + LK, no sync ====
// CTA owns a 2x8 block tile (16 blocks); computes vectors for all 40 blocks of
// the 4x10 clamped neighborhood locally -> median needs NO cross-CTA data.
__global__ void __launch_bounds__(256) mf_kernel(float* __restrict__ out) {
    __shared__ unsigned winq[40][24];   // prev_q: rows sy*16-12.., cols sx*64-12.. (88B used)
    __shared__ unsigned tqs[32][20];    // cur_q:  rows sy*16-8..,  cols sx*64-8..  (80B used)
    __shared__ float    cb[18][68];     // cur_blur halo for owned 16x? tile (66 used)
    __shared__ unsigned vpack[4][10];   // packed vectors of the neighborhood

    const int tid = threadIdx.x;
    const int sx  = blockIdx.x;         // 0..14
    const int sy  = blockIdx.y;         // 0..33
    const int wid  = tid >> 5;
    const int lane = tid & 31;

    const int rowW = sy * 16 - 12;      // winq pixel-row base
    const int colW = sx * 64 - 12;      // winq pixel-col base (bytes)
    const int rowT = sy * 16 - 8;       // tqs  pixel-row base
    const int colT = sx * 64 - 8;       // tqs  pixel-col base

    cudaGridDependencySynchronize();    // PDL: wait for blur

    // ---- load prev_q window 40 x 88B ----
    {
        const bool interior = (sy >= 1 && sy <= 32 && sx >= 1 && sx <= 13);
        for (int i = tid; i < 40 * 22; i += 256) {
            int wy = i / 22, ww = i - wy * 22;
            unsigned v;
            if (interior) {
                v = *(const unsigned*)(g_prev_q + (rowW + wy) * W + colW + ww * 4);
            } else {
                v = 0;
                int gy = clampi(rowW + wy, 0, H - 1);
#pragma unroll
                for (int c = 0; c < 4; c++) {
                    int gx = clampi(colW + ww * 4 + c, 0, W - 1);
                    v |= (unsigned)g_prev_q[gy * W + gx] << (8 * c);
                }
            }
            winq[wy][ww] = v;
        }
    }
    // ---- load cur_q strip 32 x 80B ----
    {
        const bool interior = (sy >= 1 && sy <= 32 && sx >= 1 && sx <= 13);
        for (int i = tid; i < 32 * 20; i += 256) {
            int ty = i / 20, ww = i - ty * 20;
            unsigned v;
            if (interior) {
                v = *(const unsigned*)(g_cur_q + (rowT + ty) * W + colT + ww * 4);
            } else {
                v = 0;
                int gy = clampi(rowT + ty, 0, H - 1);
#pragma unroll
                for (int c = 0; c < 4; c++) {
                    int gx = clampi(colT + ww * 4 + c, 0, W - 1);
                    v |= (unsigned)g_cur_q[gy * W + gx] << (8 * c);
                }
            }
            tqs[ty][ww] = v;
        }
    }
    // ---- load cur_blur halo 18 x 66 (clamped) ----
    for (int i = tid; i < 18 * 66; i += 256) {
        int r = i / 66, cc = i - r * 66;
        int gy = clampi(sy * 16 - 1 + r, 0, H - 1);
        int gx = clampi(sx * 64 - 1 + cc, 0, W - 1);
        cb[r][cc] = g_cur_blur[gy * W + gx];
    }
    __syncthreads();

    // ================= Phase 1: match all 40 neighborhood blocks =============
    // warp wid handles blocks nb = wid + 8k, k = 0..4.
#pragma unroll
    for (int k = 0; k < 5; k++) {
        const int nb  = wid + k * 8;
        const int nbr = nb / 10, nbc = nb - (nb / 10) * 10;
        const int by = clampi(sy * 2 - 1 + nbr, 0, HB - 1);
        const int bx = clampi(sx * 8 - 1 + nbc, 0, WB - 1);
        const int srow0 = by * 8 - sy * 16 + 8;     // window row base in winq
        const int scol0 = bx * 8 - sx * 64 + 8;     // window col base (bytes)
        const int tw    = scol0 >> 2;               // template word col (aligned)

        unsigned key = 0xffffffffu;
#pragma unroll
        for (int j = 0; j < 3; j++) {
            int c = lane + j * 32;
            if (c < NC) {
                int cy = c / 9, cx = c - (c / 9) * 9;
                int sb = scol0 + cx;
                int k8 = (sb & 3) * 8, bw = sb >> 2;
                unsigned sad = 0;
#pragma unroll
                for (int ty = 0; ty < T; ty++) {
                    const unsigned* row = &winq[srow0 + cy + ty][0];
                    unsigned w0 = row[bw], w1 = row[bw + 1], w2 = row[bw + 2];
                    unsigned lo = __funnelshift_r(w0, w1, k8);
                    unsigned hi = __funnelshift_r(w1, w2, k8);
                    const unsigned* trow = &tqs[srow0 + ty][0];
                    sad += __vsadu4(lo, trow[tw]) + __vsadu4(hi, trow[tw + 1]);
                }
                unsigned kk = ((sad * 128u + (unsigned)c_spiral[c]) << 7) | (unsigned)c;
                key = min(key, kk);
            }
        }
#pragma unroll
        for (int s = 16; s > 0; s >>= 1)
            key = min(key, __shfl_xor_sync(0xffffffffu, key, s));

        if (lane == 0) {
            int c  = key & 127;
            int dy = c / 9 - R;
            int dx = c % 9 - R;
            // packed (vy+4) | (vx+4)<<8 with vy=-dy, vx=-dx
            vpack[nbr][nbc] = (unsigned)(4 - dy) | ((unsigned)(4 - dx) << 8);
        }
    }
    __syncthreads();

    // ================= Phase 2: median + LK for the 16 owned blocks ==========
    // warp wid handles owned blocks ob = wid*2, wid*2+1; ob = row*8+col.
    int ty, tx;
    bool act = lane < 28;
    if      (lane < 8)  { ty = 0;         tx = lane;      }
    else if (lane < 16) { ty = 7;         tx = lane - 8;  }
    else if (lane < 22) { ty = lane - 15; tx = 0;         }
    else                { ty = lane - 21; tx = 7;         }

#pragma unroll
    for (int k = 0; k < 2; k++) {
        const int ob  = wid * 2 + k;
        const int row = ob >> 3, col = ob & 7;

        unsigned md = med9u(vpack[row][col],     vpack[row][col + 1],     vpack[row][col + 2],
                            vpack[row + 1][col], vpack[row + 1][col + 1], vpack[row + 1][col + 2],
                            vpack[row + 2][col], vpack[row + 2][col + 1], vpack[row + 2][col + 2]);
        int medy = (int)(md & 0xff) - 4;
        int medx = (int)((md >> 8) & 0xff) - 4;
        int offy = -medy, offx = -medx;

        float a = 0.f, bb = 0.f, d = 0.f, p = 0.f, q = 0.f;
        if (act) {
            const int cr = row * 8 + ty;            // cb row (offset by halo -1)
            const int cc = col * 8 + tx + 1;        // cb col (center)
            float gyv = (cb[cr + 2][cc] - cb[cr][cc]) * 0.5f;
            float gxv = (cb[cr + 1][cc + 1] - cb[cr + 1][cc - 1]) * 0.5f;
            float tmpl = (float)(((const unsigned char*)&tqs[row * 8 + ty + 8][0])[col * 8 + tx + 8]) * (1.0f / 255.0f);
            float mat  = (float)(((const unsigned char*)&winq[row * 8 + ty + offy + 12][0])[col * 8 + tx + offx + 12]) * (1.0f / 255.0f);
            float diff = mat - tmpl;
            a  = gxv * gxv;
            bb = gxv * gyv;
            d  = gyv * gyv;
            p  = diff * gxv;
            q  = diff * gyv;
        }
#pragma unroll
        for (int s = 16; s > 0; s >>= 1) {
            a  += __shfl_xor_sync(0xffffffffu, a,  s);
            bb += __shfl_xor_sync(0xffffffffu, bb, s);
            d  += __shfl_xor_sync(0xffffffffu, d,  s);
            p  += __shfl_xor_sync(0xffffffffu, p,  s);
            q  += __shfl_xor_sync(0xffffffffu, q,  s);
        }
        if (lane == 0) {
            float det = a * d - bb * bb;
            bool  bad = (det <= 1e-6f);
            float sd  = bad ? 1.0f : det;
            float su  = (d * p - bb * q) / sd;
            float sv  = (a * q - bb * p) / sd;
            float subv = (bad || fabsf(sv) >= 1.0f) ? 0.0f : sv;
            float subu = (bad || fabsf(su) >= 1.0f) ? 0.0f : su;
            const int blk = (sy * 2 + row) * WB + sx * 8 + col;
            out[blk]      = (float)medy + subv;
            out[NB + blk] = (float)medx + subu;
        }
    }
}

// ---------------- entry point ------------------------------------------------
extern "C" void kernel_launch(void* const* d_in, const int* in_sizes, int n_in,
                              void* d_out, int out_size) {
    const float* cur  = (const float*)d_in[0];
    const float* prev = (const float*)d_in[1];
    float* out = (float*)d_out;

    {
        dim3 bt(32, 8);
        dim3 bg(W / 64, H / 8);          // 15 x 68
        blur_kernel<<<bg, bt>>>(cur, prev);
    }

    cudaLaunchAttribute attr[1];
    attr[0].id = cudaLaunchAttributeProgrammaticStreamSerialization;
    attr[0].val.programmaticStreamSerializationAllowed = 1;
    {
        cudaLaunchConfig_t cfg = {};
        cfg.gridDim  = dim3(15, 34, 1);  // 510 CTAs, 2x8-block tile each
        cfg.blockDim = dim3(256, 1, 1);
        cfg.dynamicSmemBytes = 0;
        cfg.stream = 0;
        cfg.attrs = attr;
        cfg.numAttrs = 1;
        cudaLaunchKernelEx(&cfg, mf_kernel, out);
    }
}

// round 14
// speedup vs baseline: 1.0986x; 1.0986x over previous
#include <cuda_runtime.h>

// Problem constants (fixed by setup_inputs: img [1,1,544,960], T=8, R=4)
#define H  544
#define W  960
#define T  8
#define R  4
#define HB (H/T)                  // 68
#define WB (W/T)                  // 120
#define NB (HB*WB)                // 8160
#define NC ((2*R+1)*(2*R+1))      // 81
#define GRID 1020                 // 7/SM x 148 SMs = 1036 >= 1020 (all resident)

// ---------------- scratch (device globals) ----------------------------------
__device__ float         g_cur_blur[H*W];
__device__ unsigned char g_cur_q[H*W];
__device__ unsigned char g_prev_q[H*W];
__device__ char2         g_vec[NB];          // (vy, vx) = (-dy, -dx)

// tree-barrier state (all monotonic -> replay-safe)
__device__ unsigned g_cnt[2][32][32];        // [barrier][group][pad to 128B line]
__device__ unsigned g_root[2];
__device__ unsigned g_rel[2];

// spiral rank LUT (row-major over (dy+R, dx+R)), precomputed for R=4
__constant__ unsigned char c_spiral[NC] = {
    74, 73, 72, 71, 70, 69, 68, 67, 66,
    75, 44, 43, 42, 41, 40, 39, 38, 65,
    76, 45, 22, 21, 20, 19, 18, 37, 64,
    77, 46, 23,  8,  7,  6, 17, 36, 63,
    78, 47, 24,  9,  1,  5, 16, 35, 62,
    79, 48, 25,  2,  3,  4, 15, 34, 61,
    80, 49, 10, 11, 12, 13, 14, 33, 60,
    81, 26, 27, 28, 29, 30, 31, 32, 59,
    50, 51, 52, 53, 54, 55, 56, 57, 58
};

__device__ __forceinline__ unsigned char quant8(float v) {
    return (unsigned char)fminf(fmaxf(rintf(v * 255.0f), 0.0f), 255.0f);
}
__device__ __forceinline__ int clampi(int v, int lo, int hi) {
    return min(max(v, lo), hi);
}

// Hierarchical grid barrier: 32-way arrival tree kills the single-line atomic
// serialization that made flat barriers cost ~4us. Monotonic counters only.
// 1020 = 28 groups of 32 + 4 groups of 31 (group = b & 31).
__device__ __forceinline__ void tree_barrier(int id, int b) {
    __syncthreads();
    if (threadIdx.x == 0) {
        __threadfence();
        int g = b & 31;
        unsigned gsz = (g < 28) ? 32u : 31u;
        unsigned t = atomicAdd(&g_cnt[id][g][0], 1u);
        unsigned epoch = t / gsz + 1u;
        if (t % gsz == gsz - 1u) {                 // group closer
            unsigned r = atomicAdd(&g_root[id], 1u);
            if ((r & 31u) == 31u)                  // root closer
                atomicMax(&g_rel[id], (r >> 5) + 1u);
        }
        while (*(volatile unsigned*)&g_rel[id] < epoch) __nanosleep(64);
        __threadfence();
    }
    __syncthreads();
}

// ---------------- packed byte-SIMD median of 9 (Paeth network) --------------
#define SWU(a,b) { unsigned _t = __vminu4(a,b); b = __vmaxu4(a,b); a = _t; }
__device__ __forceinline__ unsigned med9u(unsigned v0, unsigned v1, unsigned v2,
                                          unsigned v3, unsigned v4, unsigned v5,
                                          unsigned v6, unsigned v7, unsigned v8) {
    SWU(v1,v2) SWU(v4,v5) SWU(v7,v8)
    SWU(v0,v1) SWU(v3,v4) SWU(v6,v7)
    SWU(v1,v2) SWU(v4,v5) SWU(v7,v8)
    SWU(v0,v3) SWU(v5,v8) SWU(v4,v7)
    SWU(v3,v6) SWU(v1,v4) SWU(v2,v5)
    SWU(v4,v7) SWU(v4,v2) SWU(v6,v4)
    SWU(v4,v2)
    return v4;
}

// ============== single kernel: blur -> [bar] -> match -> [bar] -> flow =======
__global__ void __launch_bounds__(256, 7) mono_kernel(const float* __restrict__ cur,
                                                      const float* __restrict__ prev,
                                                      float* __restrict__ out) {
    __shared__ unsigned winq[16][20];   // prev_q window strip: 16 rows x 72B (+pad)
    __shared__ unsigned tq[8][16];      // cur_q strip: 8 rows x 64B
    __shared__ float    cb[10][68];     // cur_blur halo
    __shared__ char2    vecs[3][10];    // 3x10 vector neighborhood

    const int tid  = threadIdx.x;
    const int b    = blockIdx.x;        // 0..1019
    const int sy   = b / 15, sx = b % 15;
    const int x0   = sx * 64, y0 = sy * 8;
    const int wid  = tid >> 5;
    const int lane = tid & 31;

    // ======================= Phase A: blur + quantize (R9 geometry) ==========
    {
        const int x2 = (sx * 32 + lane) * 2;
        const int y  = y0 + wid;
        const int yu = max(y - 1, 0) * W;
        const int ym = y * W;
        const int yd = min(y + 1, H - 1) * W;
        const bool eL = (lane == 0), eR = (lane == 31);
        const int xe = eL ? max(x2 - 1, 0) : min(x2 + 2, W - 1);

        float2 u0 = *(const float2*)&cur [yu + x2];
        float2 m0 = *(const float2*)&cur [ym + x2];
        float2 d0 = *(const float2*)&cur [yd + x2];
        float2 u1 = *(const float2*)&prev[yu + x2];
        float2 m1 = *(const float2*)&prev[ym + x2];
        float2 d1 = *(const float2*)&prev[yd + x2];
        float eu0 = 0.f, em0 = 0.f, ed0 = 0.f, eu1 = 0.f, em1 = 0.f, ed1 = 0.f;
        if (eL || eR) {
            eu0 = cur [yu + xe]; em0 = cur [ym + xe]; ed0 = cur [yd + xe];
            eu1 = prev[yu + xe]; em1 = prev[ym + xe]; ed1 = prev[yd + xe];
        }
        {
            float v0 = (u0.x + 2.0f * m0.x + d0.x) * 0.25f;
            float v1 = (u0.y + 2.0f * m0.y + d0.y) * 0.25f;
            float ve = (eu0 + 2.0f * em0 + ed0) * 0.25f;
            float vL = __shfl_up_sync(0xffffffffu, v1, 1);
            float vR = __shfl_down_sync(0xffffffffu, v0, 1);
            if (eL) vL = ve;
            if (eR) vR = ve;
            float o0 = (vL + 2.0f * v0 + v1) * 0.25f;
            float o1 = (v0 + 2.0f * v1 + vR) * 0.25f;
            *(float2*)&g_cur_blur[ym + x2] = make_float2(o0, o1);
            *(uchar2*)&g_cur_q[ym + x2]    = make_uchar2(quant8(o0), quant8(o1));
        }
        {
            float v0 = (u1.x + 2.0f * m1.x + d1.x) * 0.25f;
            float v1 = (u1.y + 2.0f * m1.y + d1.y) * 0.25f;
            float ve = (eu1 + 2.0f * em1 + ed1) * 0.25f;
            float vL = __shfl_up_sync(0xffffffffu, v1, 1);
            float vR = __shfl_down_sync(0xffffffffu, v0, 1);
            if (eL) vL = ve;
            if (eR) vR = ve;
            float o0 = (vL + 2.0f * v0 + v1) * 0.25f;
            float o1 = (v0 + 2.0f * v1 + vR) * 0.25f;
            *(uchar2*)&g_prev_q[ym + x2]   = make_uchar2(quant8(o0), quant8(o1));
        }
    }

    tree_barrier(0, b);

    // ======================= strip smem loads (shared by match + flow) =======
    {
        const bool interior = (sy >= 1 && sy <= 66 && sx >= 1 && sx <= 13);
        for (int i = tid; i < 16 * 18; i += 256) {
            int wy = i / 18, ww = i - wy * 18;
            unsigned v;
            if (interior) {
                v = *(const unsigned*)(g_prev_q + (y0 - 4 + wy) * W + (x0 - 4) + ww * 4);
            } else {
                v = 0;
                int gy = clampi(y0 - 4 + wy, 0, H - 1);
#pragma unroll
                for (int c = 0; c < 4; c++) {
                    int gx = clampi(x0 - 4 + ww * 4 + c, 0, W - 1);
                    v |= (unsigned)g_prev_q[gy * W + gx] << (8 * c);
                }
            }
            winq[wy][ww] = v;
        }
    }
    for (int i = tid; i < 8 * 16; i += 256) {
        int ty = i >> 4, ww = i & 15;
        tq[ty][ww] = *(const unsigned*)(g_cur_q + (y0 + ty) * W + x0 + ww * 4);
    }
    for (int i = tid; i < 10 * 66; i += 256) {
        int r = i / 66, cc = i - r * 66;
        int gy = clampi(y0 - 1 + r, 0, H - 1);
        int gx = clampi(x0 - 1 + cc, 0, W - 1);
        cb[r][cc] = g_cur_blur[gy * W + gx];
    }
    __syncthreads();

    const int bx  = sx * 8 + wid;
    const int blk = sy * WB + bx;

    // ======================= Phase B: SAD match (warp per block) =============
    {
        unsigned key = 0xffffffffu;
#pragma unroll
        for (int j = 0; j < 3; j++) {
            int c = lane + j * 32;
            if (c < NC) {
                int cy = c / 9, cx = c - cy * 9;
                int sb = wid * 8 + cx;
                int k8 = (sb & 3) * 8, bw = sb >> 2;
                unsigned sad = 0;
#pragma unroll
                for (int ty = 0; ty < T; ty++) {
                    const unsigned* row = &winq[ty + cy][0];
                    unsigned w0 = row[bw], w1 = row[bw + 1], w2 = row[bw + 2];
                    unsigned lo = __funnelshift_r(w0, w1, k8);
                    unsigned hi = __funnelshift_r(w1, w2, k8);
                    sad += __vsadu4(lo, tq[ty][wid * 2]) + __vsadu4(hi, tq[ty][wid * 2 + 1]);
                }
                unsigned kk = ((sad * 128u + (unsigned)c_spiral[c]) << 7) | (unsigned)c;
                key = min(key, kk);
            }
        }
#pragma unroll
        for (int s = 16; s > 0; s >>= 1)
            key = min(key, __shfl_xor_sync(0xffffffffu, key, s));

        if (lane == 0) {
            int c  = key & 127;
            int dy = c / 9 - R;
            int dx = c % 9 - R;
            g_vec[blk] = make_char2((char)(-dy), (char)(-dx));
        }
    }

    tree_barrier(1, b);

    // ---- load 3x10 vector neighborhood ----
    if (tid < 30) {
        int r = tid / 10, c = tid - (tid / 10) * 10;
        int ny = clampi(sy - 1 + r, 0, HB - 1);
        int nx = clampi(sx * 8 - 1 + c, 0, WB - 1);
        short raw = *(const volatile short*)&g_vec[ny * WB + nx];
        char2 v; v.x = (char)(raw & 0xff); v.y = (char)((raw >> 8) & 0xff);
        vecs[r][c] = v;
    }
    __syncthreads();

    // ======================= Phase C: median + LK subpixel (all smem) ========
    unsigned a0, a1, a2, a3, a4, a5, a6, a7, a8;
    {
        char2 v;
#define PKV(r,c) (v = vecs[r][wid + c], (unsigned)(v.x + 4) | ((unsigned)(v.y + 4) << 8))
        a0 = PKV(0,0); a1 = PKV(0,1); a2 = PKV(0,2);
        a3 = PKV(1,0); a4 = PKV(1,1); a5 = PKV(1,2);
        a6 = PKV(2,0); a7 = PKV(2,1); a8 = PKV(2,2);
#undef PKV
    }
    unsigned md = med9u(a0,a1,a2,a3,a4,a5,a6,a7,a8);
    int medy = (int)(md & 0xff) - 4;
    int medx = (int)((md >> 8) & 0xff) - 4;
    int offy = -medy, offx = -medx;

    int ty, tx;
    bool act = lane < 28;
    if      (lane < 8)  { ty = 0;         tx = lane;      }
    else if (lane < 16) { ty = 7;         tx = lane - 8;  }
    else if (lane < 22) { ty = lane - 15; tx = 0;         }
    else                { ty = lane - 21; tx = 7;         }

    float a = 0.f, bb = 0.f, d = 0.f, p = 0.f, q = 0.f;
    if (act) {
        const int cl = wid * 8 + tx + 1;
        float gyv = (cb[ty + 2][cl] - cb[ty][cl]) * 0.5f;
        float gxv = (cb[ty + 1][cl + 1] - cb[ty + 1][cl - 1]) * 0.5f;
        float tmpl = (float)(((const unsigned char*)&tq[ty][0])[wid * 8 + tx]) * (1.0f / 255.0f);
        float mat = (float)(((const unsigned char*)&winq[ty + offy + 4][0])[wid * 8 + tx + offx + 4]) * (1.0f / 255.0f);
        float diff = mat - tmpl;
        a  = gxv * gxv;
        bb = gxv * gyv;
        d  = gyv * gyv;
        p  = diff * gxv;
        q  = diff * gyv;
    }
#pragma unroll
    for (int s = 16; s > 0; s >>= 1) {
        a  += __shfl_xor_sync(0xffffffffu, a,  s);
        bb += __shfl_xor_sync(0xffffffffu, bb, s);
        d  += __shfl_xor_sync(0xffffffffu, d,  s);
        p  += __shfl_xor_sync(0xffffffffu, p,  s);
        q  += __shfl_xor_sync(0xffffffffu, q,  s);
    }
    if (lane == 0) {
        float det = a * d - bb * bb;
        bool  bad = (det <= 1e-6f);
        float sd  = bad ? 1.0f : det;
        float su  = (d * p - bb * q) / sd;
        float sv  = (a * q - bb * p) / sd;
        float subv = (bad || fabsf(sv) >= 1.0f) ? 0.0f : sv;
        float subu = (bad || fabsf(su) >= 1.0f) ? 0.0f : su;
        out[blk]      = (float)medy + subv;
        out[NB + blk] = (float)medx + subu;
    }
}

// ---------------- entry point ------------------------------------------------
extern "C" void kernel_launch(void* const* d_in, const int* in_sizes, int n_in,
                              void* d_out, int out_size) {
    const float* cur  = (const float*)d_in[0];
    const float* prev = (const float*)d_in[1];
    float* out = (float*)d_out;
    mono_kernel<<<GRID, 256>>>(cur, prev, out);
}

// round 15
// speedup vs baseline: 1.1931x; 1.0860x over previous
#include <cuda_runtime.h>

// Problem constants (fixed by setup_inputs: img [1,1,544,960], T=8, R=4)
#define H  544
#define W  960
#define T  8
#define R  4
#define HB (H/T)                  // 68
#define WB (W/T)                  // 120
#define NB (HB*WB)                // 8160
#define NC ((2*R+1)*(2*R+1))      // 81

// ---------------- scratch (device globals) ----------------------------------
__device__ float         g_cur_blur[H*W];
__device__ unsigned char g_cur_q[H*W];
__device__ unsigned char g_prev_q[H*W];
__device__ char2         g_vec[NB];          // (vy, vx) = (-dy, -dx)

// spiral rank LUT (row-major over (dy+R, dx+R)), precomputed for R=4
__constant__ unsigned char c_spiral[NC] = {
    74, 73, 72, 71, 70, 69, 68, 67, 66,
    75, 44, 43, 42, 41, 40, 39, 38, 65,
    76, 45, 22, 21, 20, 19, 18, 37, 64,
    77, 46, 23,  8,  7,  6, 17, 36, 63,
    78, 47, 24,  9,  1,  5, 16, 35, 62,
    79, 48, 25,  2,  3,  4, 15, 34, 61,
    80, 49, 10, 11, 12, 13, 14, 33, 60,
    81, 26, 27, 28, 29, 30, 31, 32, 59,
    50, 51, 52, 53, 54, 55, 56, 57, 58
};

__device__ __forceinline__ unsigned char quant8(float v) {
    return (unsigned char)fminf(fmaxf(rintf(v * 255.0f), 0.0f), 255.0f);
}
__device__ __forceinline__ int clampi(int v, int lo, int hi) {
    return min(max(v, lo), hi);
}

// ================= kernel 1: binomial blur + quantize ========================
// blockIdx.z selects image; 256-thread CTAs (32x8), warp = one 64px row.
__global__ void __launch_bounds__(256) blur_kernel(const float* __restrict__ cur,
                                                   const float* __restrict__ prev) {
    const int lane = threadIdx.x;
    const int x2   = (blockIdx.x * 32 + lane) * 2;            // W = 15*64
    const int y    = blockIdx.y * 8 + threadIdx.y;            // H = 68*8
    const int im   = blockIdx.z;
    const float* __restrict__ img = im ? prev : cur;

    const int yu = max(y - 1, 0) * W;
    const int ym = y * W;
    const int yd = min(y + 1, H - 1) * W;
    const bool eL = (lane == 0), eR = (lane == 31);
    const int xe = eL ? max(x2 - 1, 0) : min(x2 + 2, W - 1);

    // hoist all loads (3 vector + up to 3 edge scalars)
    float2 u = *(const float2*)&img[yu + x2];
    float2 m = *(const float2*)&img[ym + x2];
    float2 d = *(const float2*)&img[yd + x2];
    float eu = 0.f, em = 0.f, ed = 0.f;
    if (eL || eR) { eu = img[yu + xe]; em = img[ym + xe]; ed = img[yd + xe]; }

    float v0 = (u.x + 2.0f * m.x + d.x) * 0.25f;
    float v1 = (u.y + 2.0f * m.y + d.y) * 0.25f;
    float ve = (eu + 2.0f * em + ed) * 0.25f;
    float vL = __shfl_up_sync(0xffffffffu, v1, 1);
    float vR = __shfl_down_sync(0xffffffffu, v0, 1);
    if (eL) vL = ve;
    if (eR) vR = ve;
    float o0 = (vL + 2.0f * v0 + v1) * 0.25f;
    float o1 = (v0 + 2.0f * v1 + vR) * 0.25f;
    if (im == 0) {
        *(float2*)&g_cur_blur[ym + x2] = make_float2(o0, o1);
        *(uchar2*)&g_cur_q[ym + x2]    = make_uchar2(quant8(o0), quant8(o1));
    } else {
        *(uchar2*)&g_prev_q[ym + x2]   = make_uchar2(quant8(o0), quant8(o1));
    }
    cudaTriggerProgrammaticLaunchCompletion();
}

// ================= kernel 2: SAD match, strip-coalesced smem (R9) ============
__global__ void __launch_bounds__(256) match_kernel() {
    __shared__ unsigned winq[16][20];   // prev_q window strip: 16 rows x 72B (+pad)
    __shared__ unsigned tq[8][16];      // cur_q strip: 8 rows x 64B

    const int tid  = threadIdx.x;
    const int b    = blockIdx.x;        // 0..1019
    const int sy   = b / 15, sx = b % 15;
    const int x0   = sx * 64, y0 = sy * 8;
    const int wid  = tid >> 5;
    const int lane = tid & 31;

    cudaGridDependencySynchronize();    // PDL: wait for blur

    {
        const bool interior = (sy >= 1 && sy <= 66 && sx >= 1 && sx <= 13);
        for (int i = tid; i < 16 * 18; i += 256) {
            int wy = i / 18, ww = i - wy * 18;
            unsigned v;
            if (interior) {
                v = *(const unsigned*)(g_prev_q + (y0 - 4 + wy) * W + (x0 - 4) + ww * 4);
            } else {
                v = 0;
                int gy = clampi(y0 - 4 + wy, 0, H - 1);
#pragma unroll
                for (int c = 0; c < 4; c++) {
                    int gx = clampi(x0 - 4 + ww * 4 + c, 0, W - 1);
                    v |= (unsigned)g_prev_q[gy * W + gx] << (8 * c);
                }
            }
            winq[wy][ww] = v;
        }
    }
    for (int i = tid; i < 8 * 16; i += 256) {
        int ty = i >> 4, ww = i & 15;
        tq[ty][ww] = *(const unsigned*)(g_cur_q + (y0 + ty) * W + x0 + ww * 4);
    }
    __syncthreads();

    unsigned key = 0xffffffffu;
#pragma unroll
    for (int j = 0; j < 3; j++) {
        int c = lane + j * 32;
        if (c < NC) {
            int cy = c / 9, cx = c - cy * 9;
            int sb = wid * 8 + cx;
            int k8 = (sb & 3) * 8, bw = sb >> 2;
            unsigned sad = 0;
#pragma unroll
            for (int ty = 0; ty < T; ty++) {
                const unsigned* row = &winq[ty + cy][0];
                unsigned w0 = row[bw], w1 = row[bw + 1], w2 = row[bw + 2];
                unsigned lo = __funnelshift_r(w0, w1, k8);
                unsigned hi = __funnelshift_r(w1, w2, k8);
                sad += __vsadu4(lo, tq[ty][wid * 2]) + __vsadu4(hi, tq[ty][wid * 2 + 1]);
            }
            unsigned kk = ((sad * 128u + (unsigned)c_spiral[c]) << 7) | (unsigned)c;
            key = min(key, kk);
        }
    }
#pragma unroll
    for (int s = 16; s > 0; s >>= 1)
        key = min(key, __shfl_xor_sync(0xffffffffu, key, s));

    if (lane == 0) {
        int c  = key & 127;
        int dy = c / 9 - R;
        int dx = c % 9 - R;
        g_vec[sy * WB + sx * 8 + wid] = make_char2((char)(-dy), (char)(-dx));
    }
    cudaTriggerProgrammaticLaunchCompletion();
}

// ---------------- packed byte-SIMD median of 9 (Paeth network) --------------
#define SWU(a,b) { unsigned _t = __vminu4(a,b); b = __vmaxu4(a,b); a = _t; }
__device__ __forceinline__ unsigned med9u(unsigned v0, unsigned v1, unsigned v2,
                                          unsigned v3, unsigned v4, unsigned v5,
                                          unsigned v6, unsigned v7, unsigned v8) {
    SWU(v1,v2) SWU(v4,v5) SWU(v7,v8)
    SWU(v0,v1) SWU(v3,v4) SWU(v6,v7)
    SWU(v1,v2) SWU(v4,v5) SWU(v7,v8)
    SWU(v0,v3) SWU(v5,v8) SWU(v4,v7)
    SWU(v3,v6) SWU(v1,v4) SWU(v2,v5)
    SWU(v4,v7) SWU(v4,v2) SWU(v6,v4)
    SWU(v4,v2)
    return v4;
}

// ================= kernel 3: median + LK subpixel + flow output (R9) =========
__global__ void __launch_bounds__(256) flow_kernel(float* __restrict__ out) {
    const int wid  = threadIdx.x >> 5;
    const int lane = threadIdx.x & 31;
    const int blk  = blockIdx.x * 8 + wid;       // NB = 1020*8 exactly
    const int by = blk / WB, bx = blk % WB;

    int ty, tx;
    bool act = lane < 28;
    if      (lane < 8)  { ty = 0;         tx = lane;      }
    else if (lane < 16) { ty = 7;         tx = lane - 8;  }
    else if (lane < 22) { ty = lane - 15; tx = 0;         }
    else                { ty = lane - 21; tx = 7;         }
    const int gy0 = by * T + ty, gx0 = bx * T + tx;

    cudaGridDependencySynchronize();             // wait for match results

    unsigned pk = 0;
    if (lane < 9) {
        int ny = clampi(by + lane / 3 - 1, 0, HB - 1);
        int nx = clampi(bx + lane % 3 - 1, 0, WB - 1);
        char2 v = g_vec[ny * WB + nx];
        pk = (unsigned)(v.x + 4) | ((unsigned)(v.y + 4) << 8);
    }
    unsigned a0 = __shfl_sync(0xffffffffu, pk, 0);
    unsigned a1 = __shfl_sync(0xffffffffu, pk, 1);
    unsigned a2 = __shfl_sync(0xffffffffu, pk, 2);
    unsigned a3 = __shfl_sync(0xffffffffu, pk, 3);
    unsigned a4 = __shfl_sync(0xffffffffu, pk, 4);
    unsigned a5 = __shfl_sync(0xffffffffu, pk, 5);
    unsigned a6 = __shfl_sync(0xffffffffu, pk, 6);
    unsigned a7 = __shfl_sync(0xffffffffu, pk, 7);
    unsigned a8 = __shfl_sync(0xffffffffu, pk, 8);
    unsigned md = med9u(a0,a1,a2,a3,a4,a5,a6,a7,a8);
    int medy = (int)(md & 0xff) - 4;
    int medx = (int)((md >> 8) & 0xff) - 4;
    int offy = -medy, offx = -medx;

    float a = 0.f, b = 0.f, d = 0.f, p = 0.f, q = 0.f;
    if (act) {
        float gyv = (g_cur_blur[min(gy0 + 1, H - 1) * W + gx0] -
                     g_cur_blur[max(gy0 - 1, 0)     * W + gx0]) * 0.5f;
        float gxv = (g_cur_blur[gy0 * W + min(gx0 + 1, W - 1)] -
                     g_cur_blur[gy0 * W + max(gx0 - 1, 0)]) * 0.5f;
        float tmpl = (float)g_cur_q[gy0 * W + gx0] * (1.0f / 255.0f);
        int my = clampi(gy0 + offy, 0, H - 1);
        int mx = clampi(gx0 + offx, 0, W - 1);
        float mat  = (float)g_prev_q[my * W + mx] * (1.0f / 255.0f);
        float diff = mat - tmpl;
        a = gxv * gxv;
        b = gxv * gyv;
        d = gyv * gyv;
        p = diff * gxv;
        q = diff * gyv;
    }
#pragma unroll
    for (int s = 16; s > 0; s >>= 1) {
        a += __shfl_xor_sync(0xffffffffu, a, s);
        b += __shfl_xor_sync(0xffffffffu, b, s);
        d += __shfl_xor_sync(0xffffffffu, d, s);
        p += __shfl_xor_sync(0xffffffffu, p, s);
        q += __shfl_xor_sync(0xffffffffu, q, s);
    }
    if (lane == 0) {
        float det = a * d - b * b;
        bool  bad = (det <= 1e-6f);
        float sd  = bad ? 1.0f : det;
        float su  = (d * p - b * q) / sd;
        float sv  = (a * q - b * p) / sd;
        float subv = (bad || fabsf(sv) >= 1.0f) ? 0.0f : sv;
        float subu = (bad || fabsf(su) >= 1.0f) ? 0.0f : su;
        out[blk]      = (float)medy + subv;
        out[NB + blk] = (float)medx + subu;
    }
}

// ---------------- entry point ------------------------------------------------
extern "C" void kernel_launch(void* const* d_in, const int* in_sizes, int n_in,
                              void* d_out, int out_size) {
    const float* cur  = (const float*)d_in[0];
    const float* prev = (const float*)d_in[1];
    float* out = (float*)d_out;

    {
        dim3 bt(32, 8);
        dim3 bg(W / 64, H / 8, 2);       // 15 x 68 x 2 = 2040 CTAs (256 thr)
        blur_kernel<<<bg, bt>>>(cur, prev);
    }

    cudaLaunchAttribute attr[1];
    attr[0].id = cudaLaunchAttributeProgrammaticStreamSerialization;
    attr[0].val.programmaticStreamSerializationAllowed = 1;
    {
        cudaLaunchConfig_t cfg = {};
        cfg.gridDim  = dim3(1020, 1, 1);
        cfg.blockDim = dim3(256, 1, 1);
        cfg.dynamicSmemBytes = 0;
        cfg.stream = 0;
        cfg.attrs = attr;
        cfg.numAttrs = 1;
        cudaLaunchKernelEx(&cfg, match_kernel);
    }
    {
        cudaLaunchConfig_t cfg = {};
        cfg.gridDim  = dim3(NB / 8, 1, 1);
        cfg.blockDim = dim3(256, 1, 1);
        cfg.dynamicSmemBytes = 0;
        cfg.stream = 0;
        cfg.attrs = attr;
        cfg.numAttrs = 1;
        cudaLaunchKernelEx(&cfg, flow_kernel, out);
    }
}